// round 1
// baseline (speedup 1.0000x reference)
#include <cuda_runtime.h>

// ---------------------------------------------------------------------------
// MoE AG-scatter grouped GEMM, fp32 SIMT baseline.
//   out[s, :] = x[token_of_row[s], :] @ W[expert_of_row[s], :, :]^T
// Rows s are expert-sorted; splits[] gives per-expert counts.
// Shapes: x [8192,1024] f32, W [8,1024,1024] f32 (N,K with K contiguous),
//         scatter_index [8192,2] i32, splits [8] i32, out [16384,1024] f32.
// ---------------------------------------------------------------------------

#define NTOK   8192
#define TOPK   2
#define MTOT   (NTOK * TOPK)     // 16384 output rows
#define NDIM   1024
#define KDIM   1024
#define NEXP   8

#define BM 128
#define BN 128
#define BK 8
#define MAXTILES (MTOT / BM + NEXP)   // 136 upper bound on single-expert M-tiles

// Scratch (no allocations allowed): device globals.
__device__ int g_token_of_row[MTOT];
__device__ int g_tile_e[MAXTILES];
__device__ int g_tile_row0[MAXTILES];
__device__ int g_tile_rows[MAXTILES];

// ---------------------------------------------------------------------------
// Setup kernel 1: invert scatter_index.
// scatter_index.flat[f] = output row of flat slot f  =>  token_of_row[s] = f/TOPK
// scatter is a permutation of [0, MTOT), so every row gets written.
// ---------------------------------------------------------------------------
__global__ void build_token_map(const int* __restrict__ scatter) {
    int f = blockIdx.x * blockDim.x + threadIdx.x;
    if (f < MTOT) {
        g_token_of_row[scatter[f]] = f / TOPK;
    }
}

// ---------------------------------------------------------------------------
// Setup kernel 2: build per-expert M-tile table so each GEMM block handles a
// single expert. Trivial serial work (E=8, <=136 tiles).
// ---------------------------------------------------------------------------
__global__ void build_tiles(const int* __restrict__ splits) {
    if (blockIdx.x != 0 || threadIdx.x != 0) return;
    int cum = 0;
    int t = 0;
    for (int e = 0; e < NEXP; e++) {
        int cnt = splits[e];
        for (int r0 = 0; r0 < cnt; r0 += BM) {
            g_tile_e[t] = e;
            g_tile_row0[t] = cum + r0;
            g_tile_rows[t] = (cnt - r0 < BM) ? (cnt - r0) : BM;
            t++;
        }
        cum += cnt;
    }
    for (; t < MAXTILES; t++) g_tile_rows[t] = 0;
}

// ---------------------------------------------------------------------------
// Main GEMM: 128x128 block tile, BK=8, 256 threads, 8x8 register micro-tile.
// A rows are gathered via g_token_of_row; B tile comes from one expert's W.
// ---------------------------------------------------------------------------
__global__ __launch_bounds__(256, 2) void moe_gemm(
    const float* __restrict__ x,
    const float* __restrict__ w,
    float* __restrict__ out)
{
    const int tile  = blockIdx.y;
    const int nrows = g_tile_rows[tile];
    if (nrows == 0) return;
    const int row0 = g_tile_row0[tile];
    const int e    = g_tile_e[tile];
    const int n0   = blockIdx.x * BN;

    __shared__ float As[BK][BM];
    __shared__ float Bs[BK][BN];

    const int tid = threadIdx.x;

    // Load mapping: 256 threads cover 128 rows x 8 k-floats (two float4 per row).
    const int lr = tid >> 1;            // 0..127 : row within tile
    const int lk = (tid & 1) * 4;       // 0 or 4 : k-offset of this thread's float4

    // Gathered A source row (clamp out-of-range rows to token 0; never stored).
    const int tok = (lr < nrows) ? g_token_of_row[row0 + lr] : 0;
    const float* __restrict__ arow = x + (size_t)tok * KDIM;
    const float* __restrict__ brow = w + ((size_t)e * NDIM + (n0 + lr)) * KDIM;

    // Compute mapping: 16x16 thread grid, each thread owns 8x8 outputs.
    const int tx = tid & 15;            // col group
    const int ty = tid >> 4;            // row group

    float acc[8][8];
    #pragma unroll
    for (int i = 0; i < 8; i++)
        #pragma unroll
        for (int j = 0; j < 8; j++)
            acc[i][j] = 0.0f;

    for (int k0 = 0; k0 < KDIM; k0 += BK) {
        const float4 av = *(const float4*)(arow + k0 + lk);
        const float4 bv = *(const float4*)(brow + k0 + lk);

        __syncthreads();   // previous iteration's compute must finish before overwrite
        As[lk + 0][lr] = av.x;
        As[lk + 1][lr] = av.y;
        As[lk + 2][lr] = av.z;
        As[lk + 3][lr] = av.w;
        Bs[lk + 0][lr] = bv.x;
        Bs[lk + 1][lr] = bv.y;
        Bs[lk + 2][lr] = bv.z;
        Bs[lk + 3][lr] = bv.w;
        __syncthreads();

        #pragma unroll
        for (int kk = 0; kk < BK; kk++) {
            float ra[8], rb[8];
            #pragma unroll
            for (int i = 0; i < 8; i++) ra[i] = As[kk][ty * 8 + i];
            #pragma unroll
            for (int j = 0; j < 8; j++) rb[j] = Bs[kk][tx * 8 + j];
            #pragma unroll
            for (int i = 0; i < 8; i++)
                #pragma unroll
                for (int j = 0; j < 8; j++)
                    acc[i][j] = fmaf(ra[i], rb[j], acc[i][j]);
        }
    }

    // Store 8x8 micro-tile as two float4s per row.
    #pragma unroll
    for (int i = 0; i < 8; i++) {
        const int m = ty * 8 + i;
        if (m < nrows) {
            float* orow = out + (size_t)(row0 + m) * NDIM + n0 + tx * 8;
            float4 v0 = make_float4(acc[i][0], acc[i][1], acc[i][2], acc[i][3]);
            float4 v1 = make_float4(acc[i][4], acc[i][5], acc[i][6], acc[i][7]);
            *(float4*)(orow + 0) = v0;
            *(float4*)(orow + 4) = v1;
        }
    }
}

extern "C" void kernel_launch(void* const* d_in, const int* in_sizes, int n_in,
                              void* d_out, int out_size) {
    const float* x       = (const float*)d_in[0];   // [8192,1024] f32
    const float* weights = (const float*)d_in[1];   // [8,1024,1024] f32
    const int*   scatter = (const int*)d_in[2];     // [8192,2] i32
    const int*   splits  = (const int*)d_in[3];     // [8] i32
    float*       out     = (float*)d_out;           // [16384,1024] f32

    (void)in_sizes; (void)n_in; (void)out_size;

    build_token_map<<<(MTOT + 255) / 256, 256>>>(scatter);
    build_tiles<<<1, 1>>>(splits);

    dim3 grid(NDIM / BN, MAXTILES);   // (8, 136)
    moe_gemm<<<grid, 256>>>(x, weights, out);
}

// round 3
// speedup vs baseline: 2.6979x; 2.6979x over previous
#include <cuda_runtime.h>
#include <cuda_bf16.h>
#include <cstdint>

// ===========================================================================
// MoE AG-scatter grouped GEMM via mma.sync (HMMA) bf16 with 2-term fp32 split.
//   out[s,:] = x[token(s),:] @ W[e(s),:,:]^T   (fp32 in/out)
// NOTE: harness PTX target is plain sm_103 (no 'a') -> tcgen05 unavailable.
// Numerics: v ~= hi + lo (bf16 each, ~17 mantissa bits), D = Ah*Bh+Ah*Bl+Al*Bh
// accumulated in fp32 by mma.sync.m16n8k16.  Expected rel_err ~1e-5.
// Tiling: CTA 128x128x32, 8 warps (4M x 2N), warp tile 32x64,
// double-buffered cp.async, ldmatrix from 80B-stride padded smem.
// ===========================================================================

#define NTOK   8192
#define TOPK   2
#define MTOT   (NTOK * TOPK)          // 16384
#define NDIM   1024
#define KDIM   1024
#define NEXP   8

#define BM     128
#define BN     128
#define BK     32                     // bf16 k per chunk
#define NCHUNK (KDIM / BK)            // 32
#define MAXTILES (MTOT / BM + NEXP)   // 136

#define ASTR   80                     // smem row stride bytes (32*2 + 16 pad)
#define OFF_AH 0
#define OFF_AL (128 * ASTR)           // 10240
#define OFF_BH (2 * 128 * ASTR)
#define OFF_BL (3 * 128 * ASTR)
#define STAGE_BYTES (4 * 128 * ASTR)  // 40960
#define SMEM_TOTAL  (2 * STAGE_BYTES) // 81920

// ---------------- device-global scratch ------------------------------------
__device__ int g_token_of_row[MTOT];
__device__ int g_tile_e[MAXTILES];
__device__ int g_tile_row0[MAXTILES];
__device__ int g_tile_rows[MAXTILES];
__device__ __align__(16) __nv_bfloat16 g_A_hi[(size_t)MTOT * KDIM];
__device__ __align__(16) __nv_bfloat16 g_A_lo[(size_t)MTOT * KDIM];
__device__ __align__(16) __nv_bfloat16 g_W_hi[(size_t)NEXP * NDIM * KDIM];
__device__ __align__(16) __nv_bfloat16 g_W_lo[(size_t)NEXP * NDIM * KDIM];

// ---------------- helpers ---------------------------------------------------
__device__ __forceinline__ uint32_t smem_to_u32(const void* p) {
    uint32_t a;
    asm("{ .reg .u64 t; cvta.to.shared.u64 t, %1; cvt.u32.u64 %0, t; }"
        : "=r"(a) : "l"(p));
    return a;
}

#define CPA16(dst_u32, src_ptr) \
    asm volatile("cp.async.cg.shared.global [%0], [%1], 16;" \
        :: "r"(dst_u32), "l"(src_ptr))
#define CPA_COMMIT() asm volatile("cp.async.commit_group;")
#define CPA_WAIT1()  asm volatile("cp.async.wait_group 1;")
#define CPA_WAIT0()  asm volatile("cp.async.wait_group 0;")

__device__ __forceinline__ void ldsm_x4(uint32_t r[4], uint32_t addr) {
    asm volatile("ldmatrix.sync.aligned.m8n8.x4.shared.b16 {%0,%1,%2,%3}, [%4];"
        : "=r"(r[0]), "=r"(r[1]), "=r"(r[2]), "=r"(r[3]) : "r"(addr));
}

__device__ __forceinline__ void mma_bf16(float d[4],
    uint32_t a0, uint32_t a1, uint32_t a2, uint32_t a3,
    uint32_t b0, uint32_t b1)
{
    asm volatile(
        "mma.sync.aligned.m16n8k16.row.col.f32.bf16.bf16.f32 "
        "{%0,%1,%2,%3}, {%4,%5,%6,%7}, {%8,%9}, {%0,%1,%2,%3};"
        : "+f"(d[0]), "+f"(d[1]), "+f"(d[2]), "+f"(d[3])
        : "r"(a0), "r"(a1), "r"(a2), "r"(a3), "r"(b0), "r"(b1));
}

// ---------------- prep kernels ----------------------------------------------
__global__ void build_token_map(const int* __restrict__ scatter) {
    int f = blockIdx.x * blockDim.x + threadIdx.x;
    if (f < MTOT) g_token_of_row[scatter[f]] = f / TOPK;
}

__global__ void build_tiles(const int* __restrict__ splits) {
    if (threadIdx.x != 0) return;
    int cum = 0, t = 0;
    for (int e = 0; e < NEXP; e++) {
        int cnt = splits[e];
        for (int r0 = 0; r0 < cnt; r0 += BM) {
            g_tile_e[t] = e;
            g_tile_row0[t] = cum + r0;
            g_tile_rows[t] = (cnt - r0 < BM) ? (cnt - r0) : BM;
            t++;
        }
        cum += cnt;
    }
    for (; t < MAXTILES; t++) g_tile_rows[t] = 0;
}

__global__ __launch_bounds__(256) void gather_split_A(const float* __restrict__ x) {
    int idx = blockIdx.x * 256 + threadIdx.x;
    int s  = idx >> 8;
    int kq = (idx & 255) * 4;
    int t  = g_token_of_row[s];
    float4 v = *(const float4*)(x + (size_t)t * KDIM + kq);
    __nv_bfloat16 h0 = __float2bfloat16(v.x), h1 = __float2bfloat16(v.y);
    __nv_bfloat16 h2 = __float2bfloat16(v.z), h3 = __float2bfloat16(v.w);
    __nv_bfloat16 l0 = __float2bfloat16(v.x - __bfloat162float(h0));
    __nv_bfloat16 l1 = __float2bfloat16(v.y - __bfloat162float(h1));
    __nv_bfloat16 l2 = __float2bfloat16(v.z - __bfloat162float(h2));
    __nv_bfloat16 l3 = __float2bfloat16(v.w - __bfloat162float(h3));
    size_t o = (size_t)s * KDIM + kq;
    *(ushort4*)(g_A_hi + o) = make_ushort4(
        __bfloat16_as_ushort(h0), __bfloat16_as_ushort(h1),
        __bfloat16_as_ushort(h2), __bfloat16_as_ushort(h3));
    *(ushort4*)(g_A_lo + o) = make_ushort4(
        __bfloat16_as_ushort(l0), __bfloat16_as_ushort(l1),
        __bfloat16_as_ushort(l2), __bfloat16_as_ushort(l3));
}

__global__ __launch_bounds__(256) void split_W(const float* __restrict__ w) {
    int idx = blockIdx.x * 256 + threadIdx.x;
    size_t o = (size_t)idx * 4;
    float4 v = *(const float4*)(w + o);
    __nv_bfloat16 h0 = __float2bfloat16(v.x), h1 = __float2bfloat16(v.y);
    __nv_bfloat16 h2 = __float2bfloat16(v.z), h3 = __float2bfloat16(v.w);
    __nv_bfloat16 l0 = __float2bfloat16(v.x - __bfloat162float(h0));
    __nv_bfloat16 l1 = __float2bfloat16(v.y - __bfloat162float(h1));
    __nv_bfloat16 l2 = __float2bfloat16(v.z - __bfloat162float(h2));
    __nv_bfloat16 l3 = __float2bfloat16(v.w - __bfloat162float(h3));
    *(ushort4*)(g_W_hi + o) = make_ushort4(
        __bfloat16_as_ushort(h0), __bfloat16_as_ushort(h1),
        __bfloat16_as_ushort(h2), __bfloat16_as_ushort(h3));
    *(ushort4*)(g_W_lo + o) = make_ushort4(
        __bfloat16_as_ushort(l0), __bfloat16_as_ushort(l1),
        __bfloat16_as_ushort(l2), __bfloat16_as_ushort(l3));
}

// ---------------- main GEMM --------------------------------------------------
// Load one k-chunk stage: 4 tiles x 128 rows x 64B (4x16B per row).
__device__ __forceinline__ void load_stage(uint32_t sbuf, int c, int row0, int wbase, int tid)
{
    const size_t kb = (size_t)c * BK;
    #pragma unroll
    for (int i = 0; i < 8; i++) {
        int o   = tid + i * 256;          // 0..2047
        int t4  = o >> 9;                 // which tile: 0=Ah,1=Al,2=Bh,3=Bl
        int r   = (o >> 2) & 127;
        int seg = (o & 3) * 16;
        uint32_t dst = sbuf + t4 * (128 * ASTR) + r * ASTR + seg;
        const char* src;
        if (t4 < 2) {
            int gr = row0 + r; if (gr >= MTOT) gr = MTOT - 1;
            const __nv_bfloat16* base = (t4 == 0) ? g_A_hi : g_A_lo;
            src = (const char*)(base + (size_t)gr * KDIM + kb) + seg;
        } else {
            const __nv_bfloat16* base = (t4 == 2) ? g_W_hi : g_W_lo;
            src = (const char*)(base + (size_t)(wbase + r) * KDIM + kb) + seg;
        }
        CPA16(dst, src);
    }
}

__global__ __launch_bounds__(256, 2) void moe_gemm_mma(float* __restrict__ out)
{
    const int tile = blockIdx.y;
    const int nrows = g_tile_rows[tile];
    if (nrows == 0) return;
    const int row0 = g_tile_row0[tile];
    const int e    = g_tile_e[tile];
    const int n0   = blockIdx.x * BN;
    const int wbase = e * NDIM + n0;

    extern __shared__ char smem_raw[];
    const uint32_t st0 = smem_to_u32(smem_raw);
    const uint32_t st1 = st0 + STAGE_BYTES;

    const int tid  = threadIdx.x;
    const int wid  = tid >> 5;
    const int lane = tid & 31;
    const int wm   = wid & 3;         // 4 warps along M (32 rows each)
    const int wn   = wid >> 2;        // 2 warps along N (64 cols each)

    // ldmatrix per-lane address offsets (within a stage)
    // A: row = wm*32 + mt*16 + (lane&7) + ((lane>>3)&1)*8 ; col16B = lane>>4
    const int a_r   = (lane & 7) + ((lane >> 3) & 1) * 8;
    const int a_c16 = lane >> 4;
    uint32_t offA[2];
    #pragma unroll
    for (int mt = 0; mt < 2; mt++)
        offA[mt] = (wm * 32 + mt * 16 + a_r) * ASTR + a_c16 * 16;
    // B: row = wn*64 + np*16 + (lane&7) + ((lane>>4)&1)*8 ; k16B = (lane>>3)&1
    const int b_r   = (lane & 7) + ((lane >> 4) & 1) * 8;
    const int b_k16 = (lane >> 3) & 1;
    uint32_t offB[4];
    #pragma unroll
    for (int np = 0; np < 4; np++)
        offB[np] = (wn * 64 + np * 16 + b_r) * ASTR + b_k16 * 16;

    float acc[2][8][4];
    #pragma unroll
    for (int mt = 0; mt < 2; mt++)
        #pragma unroll
        for (int nt = 0; nt < 8; nt++)
            #pragma unroll
            for (int q = 0; q < 4; q++)
                acc[mt][nt][q] = 0.0f;

    // prologue: two chunks in flight
    load_stage(st0, 0, row0, wbase, tid);
    CPA_COMMIT();
    load_stage(st1, 1, row0, wbase, tid);
    CPA_COMMIT();

    for (int c = 0; c < NCHUNK; c++) {
        const uint32_t sbuf = (c & 1) ? st1 : st0;
        if (c < NCHUNK - 1) { CPA_WAIT1(); } else { CPA_WAIT0(); }
        __syncthreads();

        #pragma unroll
        for (int ks = 0; ks < 2; ks++) {
            const uint32_t ko = ks * 32;   // 16 bf16 = 32B
            uint32_t Ah[2][4], Al[2][4];
            #pragma unroll
            for (int mt = 0; mt < 2; mt++) {
                ldsm_x4(Ah[mt], sbuf + OFF_AH + offA[mt] + ko);
                ldsm_x4(Al[mt], sbuf + OFF_AL + offA[mt] + ko);
            }
            #pragma unroll
            for (int np = 0; np < 4; np++) {
                uint32_t Bh[4], Bl[4];
                ldsm_x4(Bh, sbuf + OFF_BH + offB[np] + ko);
                ldsm_x4(Bl, sbuf + OFF_BL + offB[np] + ko);
                #pragma unroll
                for (int mt = 0; mt < 2; mt++) {
                    float* d0 = acc[mt][2 * np];
                    float* d1 = acc[mt][2 * np + 1];
                    mma_bf16(d0, Ah[mt][0], Ah[mt][1], Ah[mt][2], Ah[mt][3], Bh[0], Bh[1]);
                    mma_bf16(d1, Ah[mt][0], Ah[mt][1], Ah[mt][2], Ah[mt][3], Bh[2], Bh[3]);
                    mma_bf16(d0, Ah[mt][0], Ah[mt][1], Ah[mt][2], Ah[mt][3], Bl[0], Bl[1]);
                    mma_bf16(d1, Ah[mt][0], Ah[mt][1], Ah[mt][2], Ah[mt][3], Bl[2], Bl[3]);
                    mma_bf16(d0, Al[mt][0], Al[mt][1], Al[mt][2], Al[mt][3], Bh[0], Bh[1]);
                    mma_bf16(d1, Al[mt][0], Al[mt][1], Al[mt][2], Al[mt][3], Bh[2], Bh[3]);
                }
            }
        }

        __syncthreads();
        if (c + 2 < NCHUNK) {
            load_stage(sbuf, c + 2, row0, wbase, tid);
            CPA_COMMIT();
        }
    }

    // epilogue: per mma tile, lane holds rows g and g+8, cols 2t,2t+1
    const int g = lane >> 2;
    const int t = lane & 3;
    #pragma unroll
    for (int mt = 0; mt < 2; mt++) {
        const int mBase = wm * 32 + mt * 16;
        const int m0 = mBase + g;
        const int m1 = mBase + g + 8;
        float* r0p = out + (size_t)(row0 + m0) * NDIM + n0 + wn * 64 + 2 * t;
        float* r1p = out + (size_t)(row0 + m1) * NDIM + n0 + wn * 64 + 2 * t;
        #pragma unroll
        for (int nt = 0; nt < 8; nt++) {
            if (m0 < nrows) {
                float2 v; v.x = acc[mt][nt][0]; v.y = acc[mt][nt][1];
                *(float2*)(r0p + nt * 8) = v;
            }
            if (m1 < nrows) {
                float2 v; v.x = acc[mt][nt][2]; v.y = acc[mt][nt][3];
                *(float2*)(r1p + nt * 8) = v;
            }
        }
    }
}

// ---------------------------------------------------------------------------
extern "C" void kernel_launch(void* const* d_in, const int* in_sizes, int n_in,
                              void* d_out, int out_size) {
    const float* x       = (const float*)d_in[0];
    const float* weights = (const float*)d_in[1];
    const int*   scatter = (const int*)d_in[2];
    const int*   splits  = (const int*)d_in[3];
    float*       out     = (float*)d_out;
    (void)in_sizes; (void)n_in; (void)out_size;

    cudaFuncSetAttribute(moe_gemm_mma,
                         cudaFuncAttributeMaxDynamicSharedMemorySize, SMEM_TOTAL);

    build_token_map<<<MTOT / 256, 256>>>(scatter);
    build_tiles<<<1, 32>>>(splits);
    gather_split_A<<<(MTOT * KDIM / 4) / 256, 256>>>(x);
    split_W<<<(NEXP * NDIM * KDIM / 4) / 256, 256>>>(weights);

    dim3 grid(NDIM / BN, MAXTILES);   // (8, 136)
    moe_gemm_mma<<<grid, 256, SMEM_TOTAL>>>(out);
}